// round 11
// baseline (speedup 1.0000x reference)
#include <cuda_runtime.h>
#include <cuda_bf16.h>
#include <cuda_fp8.h>
#include <stdint.h>

// Problem constants
#define N 4096
#define D 1024
#define NCLS 128

// GEMM tiling (fp8: K=128 per 128B smem row chunk)
#define BM 128
#define BN 128
#define BK 128                      // fp8 K per stage (128B/row)
#define NCHUNK (D / BK)             // 8
#define NT (N / BM)                 // 32
#define NDIAG NT                    // 32 diagonal tiles
#define NBLK (NT * (NT + 1) / 2)    // 528 upper-triangular tiles
#define NOFF (NBLK - NDIAG)         // 496 off-diagonal tiles
#define ROWB 144                    // bytes per smem row (conflict-free LDSM phases)
#define STAGE_BYTES (BM * ROWB)     // 18432 per operand
#define DYN_SMEM (2 * 2 * STAGE_BYTES + 128)

#define EMB_SCALE 32.0f             // pre-scale before e4m3; acc = 1024*cos
#define S_SCALE 2.44140625e-4f      // 0.25/1024

// Scratch (allocation-free: __device__ globals)
static __device__ __align__(16) uint8_t g_embn[N * D];   // e4m3, scaled by 32
static __device__ float g_rowsum[N];
static __device__ float g_posval[N];
static __device__ int   g_firstpos[N];
static __device__ int   g_cnt[NCLS];
static __device__ int   g_y[N];

// ---------------------------------------------------------------------------
// helpers
// ---------------------------------------------------------------------------
__device__ __forceinline__ uint32_t smem_u32(const void* p) {
    uint32_t a;
    asm("{ .reg .u64 t; cvta.to.shared.u64 t, %1; cvt.u32.u64 %0, t; }" : "=r"(a) : "l"(p));
    return a;
}
__device__ __forceinline__ void cpa16(uint32_t dst, const void* src) {
    asm volatile("cp.async.cg.shared.global [%0], [%1], 16;"
                 :: "r"(dst), "l"((unsigned long long)__cvta_generic_to_global(src)));
}
__device__ __forceinline__ void cpa_commit() { asm volatile("cp.async.commit_group;" ::: "memory"); }
template<int Nn> __device__ __forceinline__ void cpa_wait() {
    asm volatile("cp.async.wait_group %0;" :: "n"(Nn) : "memory");
}
__device__ __forceinline__ void ldsm4(uint32_t& r0, uint32_t& r1, uint32_t& r2, uint32_t& r3,
                                      uint32_t addr) {
    asm volatile("ldmatrix.sync.aligned.m8n8.x4.shared.b16 {%0,%1,%2,%3}, [%4];"
                 : "=r"(r0), "=r"(r1), "=r"(r2), "=r"(r3) : "r"(addr));
}
// fp8 e4m3 MMA: m16n8k32, f32 accum. A frag 4 regs (4 fp8 each), B frag 2 regs.
__device__ __forceinline__ void mma16832(float c[4], const uint32_t a[4], const uint32_t b[2]) {
    asm volatile(
        "mma.sync.aligned.m16n8k32.row.col.f32.e4m3.e4m3.f32 "
        "{%0,%1,%2,%3}, {%4,%5,%6,%7}, {%8,%9}, {%0,%1,%2,%3};"
        : "+f"(c[0]), "+f"(c[1]), "+f"(c[2]), "+f"(c[3])
        : "r"(a[0]), "r"(a[1]), "r"(a[2]), "r"(a[3]), "r"(b[0]), "r"(b[1]));
}

// ---------------------------------------------------------------------------
// Kernel 1: per-row L2 normalize, scale by 32, write e4m3 (packed 4B stores)
// ---------------------------------------------------------------------------
__global__ void k_norm(const float* __restrict__ in) {
    int row = blockIdx.x;
    int t = threadIdx.x;           // 256 threads, 4 consecutive elems each
    int lane = t & 31, warp = t >> 5;

    float4 v = ((const float4*)in)[row * (D / 4) + t];

    float ss = v.x*v.x + v.y*v.y + v.z*v.z + v.w*v.w;
#pragma unroll
    for (int o = 16; o > 0; o >>= 1) ss += __shfl_down_sync(0xffffffffu, ss, o);

    __shared__ float w[8];
    if (lane == 0) w[warp] = ss;
    __syncthreads();
    if (t == 0) {
        float tot = 0.f;
#pragma unroll
        for (int i = 0; i < 8; i++) tot += w[i];
        w[0] = EMB_SCALE / fmaxf(sqrtf(tot), 1e-8f);
    }
    __syncthreads();
    float inv = w[0];

    __nv_fp8_e4m3 q0(v.x * inv), q1(v.y * inv), q2(v.z * inv), q3(v.w * inv);
    uint32_t packed = (uint32_t)q0.__x | ((uint32_t)q1.__x << 8) |
                      ((uint32_t)q2.__x << 16) | ((uint32_t)q3.__x << 24);
    ((uint32_t*)g_embn)[row * (D / 4) + t] = packed;
}

// ---------------------------------------------------------------------------
// Kernel 2: label decode (int32/int64 autodetect), class counts via smem
// atomics, first/second occurrence per class, zero accumulators each replay.
// ---------------------------------------------------------------------------
__global__ void k_meta(const int* __restrict__ yraw) {
    __shared__ int cnt_s[NCLS], j0s[NCLS], j1s[NCLS];
    __shared__ int oddnz;
    int t = threadIdx.x;           // 256 threads

    if (t == 0) oddnz = 0;
    if (t < NCLS) { cnt_s[t] = 0; j0s[t] = 0x7fffffff; j1s[t] = 0x7fffffff; }
    __syncthreads();
    int local = 0;
    for (int i = t; i < 2048; i += 256)
        if (yraw[2 * i + 1] != 0) local = 1;
    if (local) atomicOr(&oddnz, 1);
    __syncthreads();
    const bool is64 = (oddnz == 0);

    for (int i = t; i < N; i += 256) {
        int v = is64 ? yraw[2 * i] : yraw[i];
        g_y[i] = v;
        atomicAdd(&cnt_s[v], 1);
        atomicMin(&j0s[v], i);
    }
    __syncthreads();
    for (int i = t; i < N; i += 256) {
        int c = g_y[i];
        if (i != j0s[c]) atomicMin(&j1s[c], i);
    }
    __syncthreads();
    if (t < NCLS) g_cnt[t] = cnt_s[t];
    for (int i = t; i < N; i += 256) {
        int c = g_y[i];
        int j1 = (j1s[c] == 0x7fffffff) ? -1 : j1s[c];
        g_firstpos[i] = (j0s[c] == i) ? j1 : j0s[c];
        g_rowsum[i] = 0.0f;
        g_posval[i] = 0.0f;
    }
}

// ---------------------------------------------------------------------------
// Kernel 3: symmetric fused fp8 GEMM, cp.async double-buffered + ldmatrix.
// Upper-triangular tiles, diagonal (cheap) tiles scheduled last.
// ---------------------------------------------------------------------------
__global__ void __launch_bounds__(256) k_gemm() {
    extern __shared__ char dynsm[];
    __shared__ int ys_r[BM], ys_c[BN], fps_r[BM], fps_c[BN];
    __shared__ float rowacc[BM], colacc[BN];

    // block id -> tile: first NOFF ids are strict-upper (br<bc), last NDIAG diag
    int br, bc;
    bool diag;
    if (blockIdx.x >= NOFF) {
        br = bc = blockIdx.x - NOFF;
        diag = true;
    } else {
        int rem = blockIdx.x;
        br = 0;
        while (rem >= NT - 1 - br) { rem -= NT - 1 - br; br++; }
        bc = br + 1 + rem;
        diag = false;
    }

    const int tid = threadIdx.x;
    const int warp = tid >> 5, lane = tid & 31;
    const int wm = warp & 3, wn = warp >> 2;      // 4 warps along M, 2 along N
    const int g = lane >> 2, t4 = lane & 3;

    if (tid < 128) {
        ys_r[tid]  = g_y[br * BM + tid];
        ys_c[tid]  = g_y[bc * BN + tid];
        fps_r[tid] = g_firstpos[br * BM + tid];
        fps_c[tid] = g_firstpos[bc * BN + tid];
        rowacc[tid] = 0.0f;
        colacc[tid] = 0.0f;
    }

    const uint32_t sb = (smem_u32(dynsm) + 127) & ~127u;
    const uint8_t* gA = g_embn + (size_t)(br * BM) * D;
    const uint8_t* gB = g_embn + (size_t)(bc * BN) * D;

    // stage fill: per operand 128 rows x 8 x 16B = 1024 chunks, 4 per thread
    const int frow = tid >> 3, fseg = tid & 7;
    auto fill = [&](int s, int c) {
        const uint32_t ab = sb + s * 2 * STAGE_BYTES;
        const uint32_t bb = ab + STAGE_BYTES;
        const int k0 = c * BK;
#pragma unroll
        for (int j = 0; j < 4; j++) {
            const int row = frow + j * 32;
            const uint32_t dst = row * ROWB + fseg * 16;
            const size_t src = (size_t)row * D + k0 + fseg * 16;
            cpa16(ab + dst, gA + src);
            cpa16(bb + dst, gB + src);
        }
        cpa_commit();
    };

    float acc[2][8][4];
#pragma unroll
    for (int i = 0; i < 2; i++)
#pragma unroll
        for (int j = 0; j < 8; j++)
#pragma unroll
            for (int e = 0; e < 4; e++) acc[i][j][e] = 0.0f;

    fill(0, 0);
    fill(1, 1);

    // ldmatrix lane addressing: lanes 0-15 -> rows, +0B; lanes 16-31 -> rows, +16B
    const int lrow = lane & 15;
    const int khalf = (lane >> 4) * 16;
    const uint32_t aoff = (wm * 32 + lrow) * ROWB + khalf;
    const uint32_t boff = (wn * 64 + lrow) * ROWB + khalf;

    for (int c = 0; c < NCHUNK; c++) {
        const int s = c & 1;
        if (c == NCHUNK - 1) cpa_wait<0>(); else cpa_wait<1>();
        __syncthreads();                     // stage s ready, visible block-wide

        const uint32_t A0 = sb + s * 2 * STAGE_BYTES + aoff;
        const uint32_t B0 = sb + s * 2 * STAGE_BYTES + STAGE_BYTES + boff;
#pragma unroll
        for (int kk = 0; kk < 4; kk++) {
            const int kb = kk * 32;          // 32 fp8 = 32B per k32-step
            uint32_t af[2][4], bfr[8][2];
            ldsm4(af[0][0], af[0][1], af[0][2], af[0][3], A0 + kb);
            ldsm4(af[1][0], af[1][1], af[1][2], af[1][3], A0 + 16 * ROWB + kb);
#pragma unroll
            for (int p = 0; p < 4; p++)      // each covers nf = 2p, 2p+1
                ldsm4(bfr[2*p][0], bfr[2*p+1][0], bfr[2*p][1], bfr[2*p+1][1],
                      B0 + p * 16 * ROWB + kb);
#pragma unroll
            for (int mf = 0; mf < 2; mf++)
#pragma unroll
                for (int nf = 0; nf < 8; nf++)
                    mma16832(acc[mf][nf], af[mf], bfr[nf]);
        }
        __syncthreads();                     // all warps done reading stage s
        if (c + 2 < NCHUNK) fill(s, c + 2);
    }

    // ---- epilogue: S = acc/4096 + 0.25; mask; exp; row (+col) sums ----
    float colpart[8][2];
#pragma unroll
    for (int nf = 0; nf < 8; nf++) { colpart[nf][0] = 0.0f; colpart[nf][1] = 0.0f; }

#pragma unroll
    for (int mf = 0; mf < 2; mf++) {
#pragma unroll
        for (int h = 0; h < 2; h++) {
            const int lr = wm * 32 + mf * 16 + h * 8 + g;
            const int yi = ys_r[lr];
            const int fpi = fps_r[lr];
            const int gr = br * BM + lr;
            float sum = 0.0f;
#pragma unroll
            for (int nf = 0; nf < 8; nf++) {
#pragma unroll
                for (int e = 0; e < 2; e++) {
                    const int lc = wn * 64 + nf * 8 + t4 * 2 + e;
                    const float S = acc[mf][nf][h * 2 + e] * S_SCALE + 0.25f;
                    float ev = (ys_c[lc] != yi) ? __expf(S) : 0.0f;
                    sum += ev;
                    if (!diag) colpart[nf][e] += ev;
                    if (bc * BN + lc == fpi) g_posval[gr] = S;            // row-side
                    if (!diag && gr == fps_c[lc]) g_posval[bc * BN + lc] = S;  // mirror
                }
            }
            sum += __shfl_xor_sync(0xffffffffu, sum, 1);
            sum += __shfl_xor_sync(0xffffffffu, sum, 2);
            if (t4 == 0) atomicAdd(&rowacc[lr], sum);
        }
    }

    if (!diag) {
#pragma unroll
        for (int nf = 0; nf < 8; nf++) {
#pragma unroll
            for (int e = 0; e < 2; e++) {
                float v = colpart[nf][e];
                v += __shfl_xor_sync(0xffffffffu, v, 4);
                v += __shfl_xor_sync(0xffffffffu, v, 8);
                v += __shfl_xor_sync(0xffffffffu, v, 16);
                if (g == 0) {
                    const int lc = wn * 64 + nf * 8 + t4 * 2 + e;
                    atomicAdd(&colacc[lc], v);
                }
            }
        }
    }

    __syncthreads();
    if (tid < 128) {
        atomicAdd(&g_rowsum[br * BM + tid], rowacc[tid]);
        if (!diag) atomicAdd(&g_rowsum[bc * BN + tid], colacc[tid]);
    }
}

// ---------------------------------------------------------------------------
// Kernel 4: final per-row lse and scalar reduce
// lse_i = log(exp(pv) + rowsum + (4094 + cnt[y_i])); loss = mean(lse - pv)
// ---------------------------------------------------------------------------
__global__ void k_final(float* __restrict__ out) {
    int t = threadIdx.x;           // 1024 threads
    int lane = t & 31, warp = t >> 5;
    float local = 0.0f;
#pragma unroll
    for (int k = 0; k < N / 1024; k++) {
        int i = t + k * 1024;
        float pv = g_posval[i];
        float rs = g_rowsum[i];
        int cnt = g_cnt[g_y[i]];
        float tot = __expf(pv) + rs + (float)(4094 + cnt);
        local += __logf(tot) - pv;
    }
#pragma unroll
    for (int o = 16; o > 0; o >>= 1) local += __shfl_down_sync(0xffffffffu, local, o);
    __shared__ float red[32];
    if (lane == 0) red[warp] = local;
    __syncthreads();
    if (t < 32) {
        float v = red[t];
#pragma unroll
        for (int o = 16; o > 0; o >>= 1) v += __shfl_down_sync(0xffffffffu, v, o);
        if (t == 0) out[0] = v * (1.0f / (float)N);
    }
}

// ---------------------------------------------------------------------------
extern "C" void kernel_launch(void* const* d_in, const int* in_sizes, int n_in,
                              void* d_out, int out_size) {
    const float* emb = (const float*)d_in[0];
    const int* yraw = (const int*)d_in[1];   // int32 or int64; k_meta detects
    float* out = (float*)d_out;

    // idempotent host-side attribute set (not an allocation; capture-legal)
    cudaFuncSetAttribute(k_gemm, cudaFuncAttributeMaxDynamicSharedMemorySize, DYN_SMEM);

    k_norm<<<N, 256>>>(emb);
    k_meta<<<1, 256>>>(yraw);
    k_gemm<<<NBLK, 256, DYN_SMEM>>>();
    k_final<<<1, 1024>>>(out);
}

// round 12
// speedup vs baseline: 1.0819x; 1.0819x over previous
#include <cuda_runtime.h>
#include <cuda_bf16.h>
#include <stdint.h>

// Problem constants
#define N 4096
#define D 1024
#define NCLS 128

// GEMM tiling
#define BM 128
#define BN 128
#define BK 64                       // K per stage (128B/row)
#define NCHUNK (D / BK)             // 16
#define NT (N / BM)                 // 32
#define NDIAG NT                    // 32 diagonal tiles
#define NBLK (NT * (NT + 1) / 2)    // 528 upper-triangular tiles
#define NOFF (NBLK - NDIAG)         // 496 off-diagonal tiles
#define ROWB 144                    // bytes per smem row (conflict-free LDSM phases)
#define STAGE_BYTES (BM * ROWB)     // 18432 per A or B panel
#define NSTAGE 3                    // 3 stages -> single __syncthreads per iter
#define DYN_SMEM (NSTAGE * 2 * STAGE_BYTES + 128)   // 110720

// Scratch (allocation-free: __device__ globals)
static __device__ __align__(16) __nv_bfloat16 g_embn[N * D];
static __device__ float g_rowsum[N];
static __device__ float g_posval[N];
static __device__ float g_zc[N];        // 4094 + cnt[y_i], precomputed
static __device__ int   g_firstpos[N];
static __device__ int   g_y[N];
static __device__ float g_part[16];

// ---------------------------------------------------------------------------
// helpers
// ---------------------------------------------------------------------------
__device__ __forceinline__ uint32_t smem_u32(const void* p) {
    uint32_t a;
    asm("{ .reg .u64 t; cvta.to.shared.u64 t, %1; cvt.u32.u64 %0, t; }" : "=r"(a) : "l"(p));
    return a;
}
__device__ __forceinline__ void cpa16(uint32_t dst, const void* src) {
    asm volatile("cp.async.cg.shared.global [%0], [%1], 16;"
                 :: "r"(dst), "l"((unsigned long long)__cvta_generic_to_global(src)));
}
__device__ __forceinline__ void cpa_commit() { asm volatile("cp.async.commit_group;" ::: "memory"); }
template<int Nn> __device__ __forceinline__ void cpa_wait() {
    asm volatile("cp.async.wait_group %0;" :: "n"(Nn) : "memory");
}
__device__ __forceinline__ void ldsm4(uint32_t& r0, uint32_t& r1, uint32_t& r2, uint32_t& r3,
                                      uint32_t addr) {
    asm volatile("ldmatrix.sync.aligned.m8n8.x4.shared.b16 {%0,%1,%2,%3}, [%4];"
                 : "=r"(r0), "=r"(r1), "=r"(r2), "=r"(r3) : "r"(addr));
}
__device__ __forceinline__ void mma16816(float c[4], const uint32_t a[4], const uint32_t b[2]) {
    asm volatile(
        "mma.sync.aligned.m16n8k16.row.col.f32.bf16.bf16.f32 "
        "{%0,%1,%2,%3}, {%4,%5,%6,%7}, {%8,%9}, {%0,%1,%2,%3};"
        : "+f"(c[0]), "+f"(c[1]), "+f"(c[2]), "+f"(c[3])
        : "r"(a[0]), "r"(a[1]), "r"(a[2]), "r"(a[3]), "r"(b[0]), "r"(b[1]));
}

// ---------------------------------------------------------------------------
// Kernel 1 (fused): blocks 0..N-1 normalize one row each; block N runs the
// label/meta pass concurrently (decode int32/int64, class counts, first-pos,
// zero accumulators, precompute g_zc). Independent work -> safe to fuse.
// ---------------------------------------------------------------------------
__global__ void k_prep(const float* __restrict__ in, const int* __restrict__ yraw) {
    if (blockIdx.x < N) {
        // ---- per-row L2 normalize, write bf16 ----
        int row = blockIdx.x;
        int t = threadIdx.x;           // 256 threads
        int lane = t & 31, warp = t >> 5;

        float v[4];
#pragma unroll
        for (int k = 0; k < 4; k++) v[k] = in[row * D + t + 256 * k];

        float ss = v[0]*v[0] + v[1]*v[1] + v[2]*v[2] + v[3]*v[3];
#pragma unroll
        for (int o = 16; o > 0; o >>= 1) ss += __shfl_down_sync(0xffffffffu, ss, o);

        __shared__ float w[8];
        if (lane == 0) w[warp] = ss;
        __syncthreads();
        if (t == 0) {
            float tot = 0.f;
#pragma unroll
            for (int i = 0; i < 8; i++) tot += w[i];
            w[0] = 1.0f / fmaxf(sqrtf(tot), 1e-8f);
        }
        __syncthreads();
        float inv = w[0];
#pragma unroll
        for (int k = 0; k < 4; k++)
            g_embn[row * D + t + 256 * k] = __float2bfloat16(v[k] * inv);
    } else {
        // ---- meta block ----
        __shared__ int cnt_s[NCLS], j0s[NCLS], j1s[NCLS];
        __shared__ int oddnz;
        int t = threadIdx.x;           // 256 threads

        if (t == 0) oddnz = 0;
        if (t < NCLS) { cnt_s[t] = 0; j0s[t] = 0x7fffffff; j1s[t] = 0x7fffffff; }
        __syncthreads();
        int local = 0;
        for (int i = t; i < 2048; i += 256)
            if (yraw[2 * i + 1] != 0) local = 1;
        if (local) atomicOr(&oddnz, 1);
        __syncthreads();
        const bool is64 = (oddnz == 0);

        for (int i = t; i < N; i += 256) {
            int v = is64 ? yraw[2 * i] : yraw[i];
            g_y[i] = v;
            atomicAdd(&cnt_s[v], 1);
            atomicMin(&j0s[v], i);
        }
        __syncthreads();
        for (int i = t; i < N; i += 256) {
            int c = g_y[i];
            if (i != j0s[c]) atomicMin(&j1s[c], i);
        }
        __syncthreads();
        for (int i = t; i < N; i += 256) {
            int c = g_y[i];
            int j1 = (j1s[c] == 0x7fffffff) ? -1 : j1s[c];
            g_firstpos[i] = (j0s[c] == i) ? j1 : j0s[c];
            g_zc[i] = (float)(4094 + cnt_s[c]);
            g_rowsum[i] = 0.0f;
            g_posval[i] = 0.0f;
        }
    }
}

// ---------------------------------------------------------------------------
// Kernel 2: symmetric fused GEMM, 3-stage cp.async pipeline (ONE sync/iter)
// + ldmatrix frags. Upper-triangular tiles, diagonal (cheap) tiles last.
// Stage safety: fill(c+2) writes stage (c-1)%3, which every warp finished
// using before passing this iteration's __syncthreads.
// ---------------------------------------------------------------------------
__global__ void __launch_bounds__(256) k_gemm() {
    extern __shared__ char dynsm[];
    __shared__ int ys_r[BM], ys_c[BN], fps_r[BM], fps_c[BN];
    __shared__ float rowacc[BM], colacc[BN];

    // block id -> tile: first NOFF ids are strict-upper (br<bc), last NDIAG diag
    int br, bc;
    bool diag;
    if (blockIdx.x >= NOFF) {
        br = bc = blockIdx.x - NOFF;
        diag = true;
    } else {
        int rem = blockIdx.x;
        br = 0;
        while (rem >= NT - 1 - br) { rem -= NT - 1 - br; br++; }
        bc = br + 1 + rem;
        diag = false;
    }

    const int tid = threadIdx.x;
    const int warp = tid >> 5, lane = tid & 31;
    const int wm = warp & 3, wn = warp >> 2;      // 4 warps along M, 2 along N
    const int g = lane >> 2, t4 = lane & 3;

    if (tid < 128) {
        ys_r[tid]  = g_y[br * BM + tid];
        ys_c[tid]  = g_y[bc * BN + tid];
        fps_r[tid] = g_firstpos[br * BM + tid];
        fps_c[tid] = g_firstpos[bc * BN + tid];
        rowacc[tid] = 0.0f;
        colacc[tid] = 0.0f;
    }

    const uint32_t sb = (smem_u32(dynsm) + 127) & ~127u;
    const __nv_bfloat16* gA = g_embn + (size_t)(br * BM) * D;
    const __nv_bfloat16* gB = g_embn + (size_t)(bc * BN) * D;

    // stage fill: per operand 128 rows x 8 x 16B chunks = 1024, 4 per thread
    const int frow = tid >> 3, fseg = tid & 7;            // rows advance by 32/iter
    auto fill = [&](int s, int c) {
        const uint32_t ab = sb + s * 2 * STAGE_BYTES;
        const uint32_t bb = ab + STAGE_BYTES;
        const int k0 = c * BK;
#pragma unroll
        for (int j = 0; j < 4; j++) {
            const int row = frow + j * 32;
            const uint32_t dst = row * ROWB + fseg * 16;
            const size_t src = (size_t)row * D + k0 + fseg * 8;
            cpa16(ab + dst, gA + src);
            cpa16(bb + dst, gB + src);
        }
        cpa_commit();
    };

    float acc[2][8][4];
#pragma unroll
    for (int i = 0; i < 2; i++)
#pragma unroll
        for (int j = 0; j < 8; j++)
#pragma unroll
            for (int e = 0; e < 4; e++) acc[i][j][e] = 0.0f;

    fill(0, 0);
    fill(1, 1);

    // ldmatrix lane addressing: lanes 0-15 -> rows, +0B; lanes 16-31 -> +16B
    const int lrow = lane & 15;
    const int khalf = (lane >> 4) * 16;
    const uint32_t aoff = (wm * 32 + lrow) * ROWB + khalf;
    const uint32_t boff = (wn * 64 + lrow) * ROWB + khalf;

    for (int c = 0; c < NCHUNK; c++) {
        if (c == NCHUNK - 1) cpa_wait<0>(); else cpa_wait<1>();
        __syncthreads();                     // chunk c resident; compute(c-1) done by all

        if (c + 2 < NCHUNK) fill((c + 2) % NSTAGE, c + 2);   // writes stage (c-1)%3: safe

        const uint32_t base = sb + (c % NSTAGE) * 2 * STAGE_BYTES;
        const uint32_t A0 = base + aoff;
        const uint32_t B0 = base + STAGE_BYTES + boff;
#pragma unroll
        for (int kk = 0; kk < 4; kk++) {
            const int kb = kk * 32;          // 16 bf16 = 32B per k-step
            uint32_t af[2][4], bfr[8][2];
            ldsm4(af[0][0], af[0][1], af[0][2], af[0][3], A0 + kb);
            ldsm4(af[1][0], af[1][1], af[1][2], af[1][3], A0 + 16 * ROWB + kb);
#pragma unroll
            for (int p = 0; p < 4; p++)      // each covers nf = 2p, 2p+1
                ldsm4(bfr[2*p][0], bfr[2*p+1][0], bfr[2*p][1], bfr[2*p+1][1],
                      B0 + p * 16 * ROWB + kb);
#pragma unroll
            for (int mf = 0; mf < 2; mf++)
#pragma unroll
                for (int nf = 0; nf < 8; nf++)
                    mma16816(acc[mf][nf], af[mf], bfr[nf]);
        }
    }

    // ---- epilogue: S = (cos+1)*0.25; mask; exp; row (+col if offdiag) sums ----
    float colpart[8][2];
#pragma unroll
    for (int nf = 0; nf < 8; nf++) { colpart[nf][0] = 0.0f; colpart[nf][1] = 0.0f; }

#pragma unroll
    for (int mf = 0; mf < 2; mf++) {
#pragma unroll
        for (int h = 0; h < 2; h++) {
            const int lr = wm * 32 + mf * 16 + h * 8 + g;
            const int yi = ys_r[lr];
            const int fpi = fps_r[lr];
            const int gr = br * BM + lr;
            float sum = 0.0f;
#pragma unroll
            for (int nf = 0; nf < 8; nf++) {
#pragma unroll
                for (int e = 0; e < 2; e++) {
                    const int lc = wn * 64 + nf * 8 + t4 * 2 + e;
                    const float S = (acc[mf][nf][h * 2 + e] + 1.0f) * 0.25f;
                    float ev = (ys_c[lc] != yi) ? __expf(S) : 0.0f;
                    sum += ev;
                    if (!diag) colpart[nf][e] += ev;
                    if (bc * BN + lc == fpi) g_posval[gr] = S;            // row-side
                    if (!diag && gr == fps_c[lc]) g_posval[bc * BN + lc] = S;  // mirror
                }
            }
            sum += __shfl_xor_sync(0xffffffffu, sum, 1);
            sum += __shfl_xor_sync(0xffffffffu, sum, 2);
            if (t4 == 0) atomicAdd(&rowacc[lr], sum);
        }
    }

    if (!diag) {
#pragma unroll
        for (int nf = 0; nf < 8; nf++) {
#pragma unroll
            for (int e = 0; e < 2; e++) {
                float v = colpart[nf][e];
                v += __shfl_xor_sync(0xffffffffu, v, 4);
                v += __shfl_xor_sync(0xffffffffu, v, 8);
                v += __shfl_xor_sync(0xffffffffu, v, 16);
                if (g == 0) {
                    const int lc = wn * 64 + nf * 8 + t4 * 2 + e;
                    atomicAdd(&colacc[lc], v);
                }
            }
        }
    }

    __syncthreads();
    if (tid < 128) {
        atomicAdd(&g_rowsum[br * BM + tid], rowacc[tid]);
        if (!diag) atomicAdd(&g_rowsum[bc * BN + tid], colacc[tid]);
    }
}

// ---------------------------------------------------------------------------
// Kernel 3a: per-row lse, 16-block partial reduce (1 row/thread)
// ---------------------------------------------------------------------------
__global__ void k_fin1() {
    int t = threadIdx.x;           // 256 threads, grid 16
    int i = blockIdx.x * 256 + t;
    int lane = t & 31, warp = t >> 5;

    float pv = g_posval[i];
    float tot = __expf(pv) + g_rowsum[i] + g_zc[i];
    float local = __logf(tot) - pv;

#pragma unroll
    for (int o = 16; o > 0; o >>= 1) local += __shfl_down_sync(0xffffffffu, local, o);
    __shared__ float red[8];
    if (lane == 0) red[warp] = local;
    __syncthreads();
    if (t == 0) {
        float v = 0.f;
#pragma unroll
        for (int k = 0; k < 8; k++) v += red[k];
        g_part[blockIdx.x] = v;
    }
}

// ---------------------------------------------------------------------------
// Kernel 3b: finisher
// ---------------------------------------------------------------------------
__global__ void k_fin2(float* __restrict__ out) {
    int t = threadIdx.x;           // 32 threads
    float v = (t < 16) ? g_part[t] : 0.0f;
#pragma unroll
    for (int o = 16; o > 0; o >>= 1) v += __shfl_down_sync(0xffffffffu, v, o);
    if (t == 0) out[0] = v * (1.0f / (float)N);
}

// ---------------------------------------------------------------------------
extern "C" void kernel_launch(void* const* d_in, const int* in_sizes, int n_in,
                              void* d_out, int out_size) {
    const float* emb = (const float*)d_in[0];
    const int* yraw = (const int*)d_in[1];   // int32 or int64; k_prep detects
    float* out = (float*)d_out;

    // idempotent host-side attribute set (not an allocation; capture-legal)
    cudaFuncSetAttribute(k_gemm, cudaFuncAttributeMaxDynamicSharedMemorySize, DYN_SMEM);

    k_prep<<<N + 1, 256>>>(emb, yraw);
    k_gemm<<<NBLK, 256, DYN_SMEM>>>();
    k_fin1<<<16, 256>>>();
    k_fin2<<<1, 32>>>(out);
}

// round 13
// speedup vs baseline: 1.1159x; 1.0314x over previous
#include <cuda_runtime.h>
#include <cuda_bf16.h>
#include <stdint.h>

// Problem constants
#define N 4096
#define D 1024
#define NCLS 128

// GEMM tiling
#define BM 128
#define BN 128
#define BK 64                       // K per stage (128B/row)
#define NCHUNK (D / BK)             // 16
#define NT (N / BM)                 // 32
#define NDIAG NT                    // 32 diagonal tiles
#define NBLK (NT * (NT + 1) / 2)    // 528 upper-triangular tiles
#define NOFF (NBLK - NDIAG)         // 496 off-diagonal tiles
#define ROWB 144                    // bytes per smem row (conflict-free LDSM phases)
#define STAGE_BYTES (BM * ROWB)     // 18432 per operand
#define DYN_SMEM (2 * 2 * STAGE_BYTES + 128)   // 73856 (R7-proven)

// Scratch (allocation-free: __device__ globals)
static __device__ __align__(16) __nv_bfloat16 g_embn[N * D];
static __device__ float g_rowsum[N];
static __device__ float g_posval[N];
static __device__ float g_zc[N];        // 4094 + cnt[y_i], precomputed
static __device__ int   g_firstpos[N];
static __device__ int   g_y[N];
static __device__ int   g_ctr;          // completed-CTA counter (reset in k_prep)

// ---------------------------------------------------------------------------
// helpers
// ---------------------------------------------------------------------------
__device__ __forceinline__ uint32_t smem_u32(const void* p) {
    uint32_t a;
    asm("{ .reg .u64 t; cvta.to.shared.u64 t, %1; cvt.u32.u64 %0, t; }" : "=r"(a) : "l"(p));
    return a;
}
__device__ __forceinline__ void cpa16(uint32_t dst, const void* src) {
    asm volatile("cp.async.cg.shared.global [%0], [%1], 16;"
                 :: "r"(dst), "l"((unsigned long long)__cvta_generic_to_global(src)));
}
__device__ __forceinline__ void cpa_commit() { asm volatile("cp.async.commit_group;" ::: "memory"); }
template<int Nn> __device__ __forceinline__ void cpa_wait() {
    asm volatile("cp.async.wait_group %0;" :: "n"(Nn) : "memory");
}
__device__ __forceinline__ void ldsm4(uint32_t& r0, uint32_t& r1, uint32_t& r2, uint32_t& r3,
                                      uint32_t addr) {
    asm volatile("ldmatrix.sync.aligned.m8n8.x4.shared.b16 {%0,%1,%2,%3}, [%4];"
                 : "=r"(r0), "=r"(r1), "=r"(r2), "=r"(r3) : "r"(addr));
}
__device__ __forceinline__ void mma16816(float c[4], const uint32_t a[4], const uint32_t b[2]) {
    asm volatile(
        "mma.sync.aligned.m16n8k16.row.col.f32.bf16.bf16.f32 "
        "{%0,%1,%2,%3}, {%4,%5,%6,%7}, {%8,%9}, {%0,%1,%2,%3};"
        : "+f"(c[0]), "+f"(c[1]), "+f"(c[2]), "+f"(c[3])
        : "r"(a[0]), "r"(a[1]), "r"(a[2]), "r"(a[3]), "r"(b[0]), "r"(b[1]));
}

// ---------------------------------------------------------------------------
// Kernel 1 (fused): blocks 0..N-1 normalize one row each; block N runs the
// label/meta pass concurrently (decode int32/int64, class counts, first-pos,
// zero accumulators + completion counter, precompute g_zc).
// ---------------------------------------------------------------------------
__global__ void k_prep(const float* __restrict__ in, const int* __restrict__ yraw) {
    if (blockIdx.x < N) {
        // ---- per-row L2 normalize, write bf16 ----
        int row = blockIdx.x;
        int t = threadIdx.x;           // 256 threads
        int lane = t & 31, warp = t >> 5;

        float v[4];
#pragma unroll
        for (int k = 0; k < 4; k++) v[k] = in[row * D + t + 256 * k];

        float ss = v[0]*v[0] + v[1]*v[1] + v[2]*v[2] + v[3]*v[3];
#pragma unroll
        for (int o = 16; o > 0; o >>= 1) ss += __shfl_down_sync(0xffffffffu, ss, o);

        __shared__ float w[8];
        if (lane == 0) w[warp] = ss;
        __syncthreads();
        if (t == 0) {
            float tot = 0.f;
#pragma unroll
            for (int i = 0; i < 8; i++) tot += w[i];
            w[0] = 1.0f / fmaxf(sqrtf(tot), 1e-8f);
        }
        __syncthreads();
        float inv = w[0];
#pragma unroll
        for (int k = 0; k < 4; k++)
            g_embn[row * D + t + 256 * k] = __float2bfloat16(v[k] * inv);
    } else {
        // ---- meta block ----
        __shared__ int cnt_s[NCLS], j0s[NCLS], j1s[NCLS];
        __shared__ int oddnz;
        int t = threadIdx.x;           // 256 threads

        if (t == 0) { oddnz = 0; g_ctr = 0; }
        if (t < NCLS) { cnt_s[t] = 0; j0s[t] = 0x7fffffff; j1s[t] = 0x7fffffff; }
        __syncthreads();
        int local = 0;
        for (int i = t; i < 2048; i += 256)
            if (yraw[2 * i + 1] != 0) local = 1;
        if (local) atomicOr(&oddnz, 1);
        __syncthreads();
        const bool is64 = (oddnz == 0);

        for (int i = t; i < N; i += 256) {
            int v = is64 ? yraw[2 * i] : yraw[i];
            g_y[i] = v;
            atomicAdd(&cnt_s[v], 1);
            atomicMin(&j0s[v], i);
        }
        __syncthreads();
        for (int i = t; i < N; i += 256) {
            int c = g_y[i];
            if (i != j0s[c]) atomicMin(&j1s[c], i);
        }
        __syncthreads();
        for (int i = t; i < N; i += 256) {
            int c = g_y[i];
            int j1 = (j1s[c] == 0x7fffffff) ? -1 : j1s[c];
            g_firstpos[i] = (j0s[c] == i) ? j1 : j0s[c];
            g_zc[i] = (float)(4094 + cnt_s[c]);
            g_rowsum[i] = 0.0f;
            g_posval[i] = 0.0f;
        }
    }
}

// ---------------------------------------------------------------------------
// Kernel 2: symmetric fused GEMM (R7-proven 2-stage cp.async + ldmatrix)
// + fused last-CTA final reduction (no separate final kernels).
// Upper-triangular tiles; diagonal (cheap) tiles scheduled last, so the
// finishing CTA is a cheap one.
// ---------------------------------------------------------------------------
__global__ void __launch_bounds__(256) k_gemm(float* __restrict__ out) {
    extern __shared__ char dynsm[];
    __shared__ int ys_r[BM], ys_c[BN], fps_r[BM], fps_c[BN];
    __shared__ float rowacc[BM], colacc[BN];
    __shared__ int s_last;

    // block id -> tile: first NOFF ids are strict-upper (br<bc), last NDIAG diag
    int br, bc;
    bool diag;
    if (blockIdx.x >= NOFF) {
        br = bc = blockIdx.x - NOFF;
        diag = true;
    } else {
        int rem = blockIdx.x;
        br = 0;
        while (rem >= NT - 1 - br) { rem -= NT - 1 - br; br++; }
        bc = br + 1 + rem;
        diag = false;
    }

    const int tid = threadIdx.x;
    const int warp = tid >> 5, lane = tid & 31;
    const int wm = warp & 3, wn = warp >> 2;      // 4 warps along M, 2 along N
    const int g = lane >> 2, t4 = lane & 3;

    if (tid < 128) {
        ys_r[tid]  = g_y[br * BM + tid];
        ys_c[tid]  = g_y[bc * BN + tid];
        fps_r[tid] = g_firstpos[br * BM + tid];
        fps_c[tid] = g_firstpos[bc * BN + tid];
        rowacc[tid] = 0.0f;
        colacc[tid] = 0.0f;
    }

    const uint32_t sb = (smem_u32(dynsm) + 127) & ~127u;
    const __nv_bfloat16* gA = g_embn + (size_t)(br * BM) * D;
    const __nv_bfloat16* gB = g_embn + (size_t)(bc * BN) * D;

    // stage fill: per operand 128 rows x 8 x 16B chunks = 1024, 4 per thread
    const int frow = tid >> 3, fseg = tid & 7;            // rows advance by 32/iter
    auto fill = [&](int s, int c) {
        const uint32_t ab = sb + s * 2 * STAGE_BYTES;
        const uint32_t bb = ab + STAGE_BYTES;
        const int k0 = c * BK;
#pragma unroll
        for (int j = 0; j < 4; j++) {
            const int row = frow + j * 32;
            const uint32_t dst = row * ROWB + fseg * 16;
            const size_t src = (size_t)row * D + k0 + fseg * 8;
            cpa16(ab + dst, gA + src);
            cpa16(bb + dst, gB + src);
        }
        cpa_commit();
    };

    float acc[2][8][4];
#pragma unroll
    for (int i = 0; i < 2; i++)
#pragma unroll
        for (int j = 0; j < 8; j++)
#pragma unroll
            for (int e = 0; e < 4; e++) acc[i][j][e] = 0.0f;

    fill(0, 0);
    fill(1, 1);

    // ldmatrix lane addressing: lanes 0-15 -> rows, +0B; lanes 16-31 -> +16B
    const int lrow = lane & 15;
    const int khalf = (lane >> 4) * 16;
    const uint32_t aoff = (wm * 32 + lrow) * ROWB + khalf;
    const uint32_t boff = (wn * 64 + lrow) * ROWB + khalf;

    for (int c = 0; c < NCHUNK; c++) {
        const int s = c & 1;
        if (c == NCHUNK - 1) cpa_wait<0>(); else cpa_wait<1>();
        __syncthreads();                     // stage s ready, visible block-wide

        const uint32_t A0 = sb + s * 2 * STAGE_BYTES + aoff;
        const uint32_t B0 = sb + s * 2 * STAGE_BYTES + STAGE_BYTES + boff;
#pragma unroll
        for (int kk = 0; kk < 4; kk++) {
            const int kb = kk * 32;          // 16 bf16 = 32B per k-step
            uint32_t af[2][4], bfr[8][2];
            ldsm4(af[0][0], af[0][1], af[0][2], af[0][3], A0 + kb);
            ldsm4(af[1][0], af[1][1], af[1][2], af[1][3], A0 + 16 * ROWB + kb);
#pragma unroll
            for (int p = 0; p < 4; p++)      // each covers nf = 2p, 2p+1
                ldsm4(bfr[2*p][0], bfr[2*p+1][0], bfr[2*p][1], bfr[2*p+1][1],
                      B0 + p * 16 * ROWB + kb);
#pragma unroll
            for (int mf = 0; mf < 2; mf++)
#pragma unroll
                for (int nf = 0; nf < 8; nf++)
                    mma16816(acc[mf][nf], af[mf], bfr[nf]);
        }
        __syncthreads();                     // all warps done reading stage s
        if (c + 2 < NCHUNK) fill(s, c + 2);
    }

    // ---- epilogue: S = (cos+1)*0.25; mask; exp; row (+col if offdiag) sums ----
    float colpart[8][2];
#pragma unroll
    for (int nf = 0; nf < 8; nf++) { colpart[nf][0] = 0.0f; colpart[nf][1] = 0.0f; }

#pragma unroll
    for (int mf = 0; mf < 2; mf++) {
#pragma unroll
        for (int h = 0; h < 2; h++) {
            const int lr = wm * 32 + mf * 16 + h * 8 + g;
            const int yi = ys_r[lr];
            const int fpi = fps_r[lr];
            const int gr = br * BM + lr;
            float sum = 0.0f;
#pragma unroll
            for (int nf = 0; nf < 8; nf++) {
#pragma unroll
                for (int e = 0; e < 2; e++) {
                    const int lc = wn * 64 + nf * 8 + t4 * 2 + e;
                    const float S = (acc[mf][nf][h * 2 + e] + 1.0f) * 0.25f;
                    float ev = (ys_c[lc] != yi) ? __expf(S) : 0.0f;
                    sum += ev;
                    if (!diag) colpart[nf][e] += ev;
                    if (bc * BN + lc == fpi) g_posval[gr] = S;            // row-side
                    if (!diag && gr == fps_c[lc]) g_posval[bc * BN + lc] = S;  // mirror
                }
            }
            sum += __shfl_xor_sync(0xffffffffu, sum, 1);
            sum += __shfl_xor_sync(0xffffffffu, sum, 2);
            if (t4 == 0) atomicAdd(&rowacc[lr], sum);
        }
    }

    if (!diag) {
#pragma unroll
        for (int nf = 0; nf < 8; nf++) {
#pragma unroll
            for (int e = 0; e < 2; e++) {
                float v = colpart[nf][e];
                v += __shfl_xor_sync(0xffffffffu, v, 4);
                v += __shfl_xor_sync(0xffffffffu, v, 8);
                v += __shfl_xor_sync(0xffffffffu, v, 16);
                if (g == 0) {
                    const int lc = wn * 64 + nf * 8 + t4 * 2 + e;
                    atomicAdd(&colacc[lc], v);
                }
            }
        }
    }

    __syncthreads();
    if (tid < 128) {
        atomicAdd(&g_rowsum[br * BM + tid], rowacc[tid]);
        if (!diag) atomicAdd(&g_rowsum[bc * BN + tid], colacc[tid]);
    }

    // ---- fused final reduction: last CTA computes the loss ----
    __threadfence();                         // rowsum/posval writes visible device-wide
    __syncthreads();                         // all threads' fences done
    if (tid == 0) s_last = (atomicAdd(&g_ctr, 1) == NBLK - 1);
    __syncthreads();
    if (s_last) {
        // all other CTAs' writes are visible (their fences precede their
        // counter increments; we observed the final increment)
        float local = 0.0f;
#pragma unroll
        for (int k = 0; k < N / 256; k++) {
            const int i = tid + k * 256;
            const float pv = g_posval[i];
            const float tot = __expf(pv) + g_rowsum[i] + g_zc[i];
            local += __logf(tot) - pv;
        }
#pragma unroll
        for (int o = 16; o > 0; o >>= 1) local += __shfl_down_sync(0xffffffffu, local, o);
        if (lane == 0) colacc[warp] = local;     // reuse smem for block reduce
        __syncthreads();
        if (tid == 0) {
            float v = 0.0f;
#pragma unroll
            for (int k = 0; k < 8; k++) v += colacc[k];
            out[0] = v * (1.0f / (float)N);
        }
    }
}

// ---------------------------------------------------------------------------
extern "C" void kernel_launch(void* const* d_in, const int* in_sizes, int n_in,
                              void* d_out, int out_size) {
    const float* emb = (const float*)d_in[0];
    const int* yraw = (const int*)d_in[1];   // int32 or int64; k_prep detects
    float* out = (float*)d_out;

    // idempotent host-side attribute set (not an allocation; capture-legal)
    cudaFuncSetAttribute(k_gemm, cudaFuncAttributeMaxDynamicSharedMemorySize, DYN_SMEM);

    k_prep<<<N + 1, 256>>>(emb, yraw);
    k_gemm<<<NBLK, 256, DYN_SMEM>>>(out);
}